// round 9
// baseline (speedup 1.0000x reference)
#include <cuda_runtime.h>

// SpatialTransformer: out[b,c,y,x] = bilinear_sample_zeros(src[b,c], y+flow[b,0,y,x], x+flow[b,1,y,x])
// src [8,64,256,256] f32, flow [8,2,256,256] f32, out [8,64,256,256] f32.
//
// SMEM-tiled gather. Each block stages a (TY+2H)x(TX+2H) src tile into shared
// memory with coalesced loads, then performs the 4-tap bilinear gather from SMEM
// (bank-scrambled via odd row stride). Weights/indices computed once per pixel,
// register-cached across CPC channels.

#define B_ 8
#define C_ 64
#define H_ 256
#define W_ 256
#define PLANE (H_ * W_)

#define TX 64
#define TY 32
#define HALO 8
#define SRW (TX + 2 * HALO)   // 80 staged cols
#define SRH (TY + 2 * HALO)   // 48 staged rows
#define SSTR 81               // smem row stride (odd -> bank scramble)
#define NTHREADS 512
#define CPC 4                 // channels per block
#define KPT (TX * TY / NTHREADS)  // 4 pixels per thread

__global__ __launch_bounds__(NTHREADS, 2) void st_tile_kernel(
    const float* __restrict__ src,
    const float* __restrict__ flow,
    float* __restrict__ out)
{
    __shared__ float sm[SRH * SSTR];   // 48*81*4 = 15552 B

    const int t    = threadIdx.x;
    const int col  = t & 63;           // 0..63 within tile
    const int rowg = t >> 6;           // 0..7
    const int tx0  = blockIdx.x * TX;
    const int ty0  = blockIdx.y * TY;
    const int zc   = blockIdx.z;       // 0..127
    const int b    = zc >> 4;          // 0..7
    const int c0   = (zc & 15) * CPC;  // 0..60

    const int row_base = ty0 - HALO;
    const int col_base = tx0 - HALO;
    const int x = tx0 + col;

    // Staging mapping: 512 threads as 80 cols x 6.4 rows -> use (t%80, t/80),
    // stride 512/80... instead use fixed 2D: thread t covers column (t % SRW)
    // and rows (t / SRW) + k*(NTHREADS/SRW). 512/80 = 6 full rows + remainder;
    // handle with generic strided loop but precomputed ry/rx increments.
    const int st_rx0 = t % SRW;        // 0..79
    const int st_ry0 = t / SRW;        // 0..6

    // ---- per-pixel prologue: flow load + weights + smem indices ----
    float W00[KPT], W01[KPT], W10[KPT], W11[KPT];
    int   I00[KPT], I01[KPT], I10[KPT], I11[KPT];

    #pragma unroll
    for (int k = 0; k < KPT; ++k) {
        const int y = ty0 + rowg + 8 * k;
        const int f = b * 2 * PLANE + y * W_ + x;
        const float py = (float)y + __ldg(flow + f);           // flow ch 0 = dy
        const float px = (float)x + __ldg(flow + f + PLANE);   // flow ch 1 = dx

        const float y0f = floorf(py), x0f = floorf(px);
        float wy1 = py - y0f, wx1 = px - x0f;
        float wy0 = 1.0f - wy1, wx0 = 1.0f - wx1;

        const int y0 = (int)y0f, x0 = (int)x0f;
        const int y1 = y0 + 1,  x1 = x0 + 1;

        // zeros padding: fold validity into the 1D weights
        wy0 = ((unsigned)y0 < (unsigned)H_) ? wy0 : 0.0f;
        wy1 = ((unsigned)y1 < (unsigned)H_) ? wy1 : 0.0f;
        wx0 = ((unsigned)x0 < (unsigned)W_) ? wx0 : 0.0f;
        wx1 = ((unsigned)x1 < (unsigned)W_) ? wx1 : 0.0f;

        W00[k] = wy0 * wx0;  W01[k] = wy0 * wx1;
        W10[k] = wy1 * wx0;  W11[k] = wy1 * wx1;

        // clamped image coords -> tile-local smem coords (clamped for safety)
        const int yc0 = min(max(y0, 0), H_ - 1);
        const int yc1 = min(max(y1, 0), H_ - 1);
        const int xc0 = min(max(x0, 0), W_ - 1);
        const int xc1 = min(max(x1, 0), W_ - 1);

        const int sy0 = min(max(yc0 - row_base, 0), SRH - 1);
        const int sy1 = min(max(yc1 - row_base, 0), SRH - 1);
        const int sx0 = min(max(xc0 - col_base, 0), SRW - 1);
        const int sx1 = min(max(xc1 - col_base, 0), SRW - 1);

        I00[k] = sy0 * SSTR + sx0;
        I01[k] = sy0 * SSTR + sx1;
        I10[k] = sy1 * SSTR + sx0;
        I11[k] = sy1 * SSTR + sx1;
    }

    // Precompute clamped global coords for the staging footprint of this thread.
    // Thread covers (st_ry0 + j*ROWS_PER_PASS, st_rx0) for j = 0..NPASS-1.
    const int ROWS_PER_PASS = NTHREADS / SRW;          // 6 (floor)
    // total elements 3840; 512 threads -> ceil(3840/512)=8 passes of stride 512
    const int gx_st = min(max(col_base + st_rx0, 0), W_ - 1);

    const int obase = (ty0 + rowg) * W_ + x;
    const float* sc = src + (size_t)(b * C_ + c0) * PLANE;
    float*       oc = out + (size_t)(b * C_ + c0) * PLANE;

    (void)ROWS_PER_PASS;

    // Precompute the (ry, rx, gy*W+gx) tuples for the up-to-8 staging passes.
    int s_smem[8];
    int s_gmem[8];
    int npass = 0;
    #pragma unroll
    for (int j = 0; j < 8; ++j) {
        const int i = t + j * NTHREADS;
        if (i < SRH * SRW) {
            const int ry = st_ry0 + j * (NTHREADS / SRW) + (st_rx0 + (j * (NTHREADS % SRW))) / SRW;
            // NOTE: the above closed form is error-prone; fall back to exact:
            const int ry_e = i / SRW;
            const int rx_e = i - ry_e * SRW;
            const int gy = min(max(row_base + ry_e, 0), H_ - 1);
            const int gx = min(max(col_base + rx_e, 0), W_ - 1);
            s_smem[npass] = ry_e * SSTR + rx_e;
            s_gmem[npass] = gy * W_ + gx;
            ++npass;
        }
    }
    (void)gx_st;

    // ---- channel loop: stage tile -> gather from smem ----
    for (int c = 0; c < CPC; ++c) {
        __syncthreads();   // previous channel's readers done before overwrite
        #pragma unroll
        for (int j = 0; j < 8; ++j) {
            if (j < npass) sm[s_smem[j]] = __ldg(sc + s_gmem[j]);
        }
        __syncthreads();

        #pragma unroll
        for (int k = 0; k < KPT; ++k) {
            const float v = W00[k] * sm[I00[k]] + W01[k] * sm[I01[k]]
                          + W10[k] * sm[I10[k]] + W11[k] * sm[I11[k]];
            oc[obase + k * (8 * W_)] = v;
        }
        sc += PLANE;
        oc += PLANE;
    }
}

extern "C" void kernel_launch(void* const* d_in, const int* in_sizes, int n_in,
                              void* d_out, int out_size)
{
    const float* src  = (const float*)d_in[0];
    const float* flow = (const float*)d_in[1];
    float* out = (float*)d_out;

    dim3 grid(W_ / TX, H_ / TY, B_ * (C_ / CPC));  // (4, 8, 128) = 4096 blocks
    dim3 block(NTHREADS);                          // 512 threads
    st_tile_kernel<<<grid, block>>>(src, flow, out);
}

// round 10
// speedup vs baseline: 1.1502x; 1.1502x over previous
#include <cuda_runtime.h>

// SpatialTransformer: out[b,c,y,x] = bilinear_sample_zeros(src[b,c], y+flow[b,0,y,x], x+flow[b,1,y,x])
// src [8,64,256,256] f32, flow [8,2,256,256] f32, out [8,64,256,256] f32.
//
// R9: R2 structure (one thread = one (b,y,x) pixel for 8 channels, warp = 32
// consecutive x) + merged same-row taps: the two x-taps of each bilinear row are
// fetched with ONE aligned LDG.128 over the 4-float window containing xa
// (cleanup LDG.32 only when xa&3==3), halving gather request count and cutting
// l1tex wavefronts (the binding pipe at 84.3% in R2).

#define B_ 8
#define C_ 64
#define H_ 256
#define W_ 256
#define PLANE (H_ * W_)
#define CPT 8   // channels per thread

__global__ __launch_bounds__(256) void st_w4_kernel(
    const float* __restrict__ src,
    const float* __restrict__ flow,
    float* __restrict__ out)
{
    const int x  = threadIdx.x;        // 0..255
    const int y  = blockIdx.x;         // 0..255
    const int cg = blockIdx.y;         // 0..7   (channel group)
    const int b  = blockIdx.z;         // 0..7

    // ---- per-(b,y,x) prologue: flow load + bilinear weights/indices ----
    const int fbase = b * 2 * PLANE + y * W_ + x;
    const float py = (float)y + __ldg(flow + fbase);           // flow ch 0 = dy
    const float px = (float)x + __ldg(flow + fbase + PLANE);   // flow ch 1 = dx

    const float y0f = floorf(py);
    const float x0f = floorf(px);
    float wy1 = py - y0f;
    float wx1 = px - x0f;
    float wy0 = 1.0f - wy1;
    float wx0 = 1.0f - wx1;

    const int y0 = (int)y0f;
    const int x0 = (int)x0f;
    const int y1 = y0 + 1;
    const int x1 = x0 + 1;

    // zeros padding folded into 1D weights (identical to the verified R2 logic)
    wy0 = ((unsigned)y0 < (unsigned)H_) ? wy0 : 0.0f;
    wy1 = ((unsigned)y1 < (unsigned)H_) ? wy1 : 0.0f;
    wx0 = ((unsigned)x0 < (unsigned)W_) ? wx0 : 0.0f;
    wx1 = ((unsigned)x1 < (unsigned)W_) ? wx1 : 0.0f;

    const float w00 = wy0 * wx0;
    const float w01 = wy0 * wx1;
    const float w10 = wy1 * wx0;
    const float w11 = wy1 * wx1;

    // clamped coords (values at invalid coords get weight 0)
    const int ya = min(max(y0, 0), H_ - 1);
    const int yb = min(max(y1, 0), H_ - 1);
    const int xa = min(max(x0, 0), W_ - 1);
    const int xb = min(max(x1, 0), W_ - 1);

    // 4-float aligned window containing xa; xb is inside unless (xa&3)==3 && xb>xa
    const int A = xa & ~3;
    const int m = xa & 3;
    const bool adv        = (xb != xa);       // xb == xa+1
    const bool need_clean = adv && (m == 3);  // xb falls outside the window

    const int rowA   = ya * W_ + A;           // window offset, row y0
    const int rowB   = yb * W_ + A;           // window offset, row y1
    const int cleanA = ya * W_ + xb;          // fallback scalar tap offsets
    const int cleanB = yb * W_ + xb;

    // ---- channel loop ----
    const int c0 = cg * CPT;
    const float* s = src + (size_t)(b * C_ + c0) * PLANE;
    float*       o = out + (size_t)(b * C_ + c0) * PLANE + y * W_ + x;

    #pragma unroll
    for (int c = 0; c < CPT; ++c) {
        const float4 qa = __ldg((const float4*)(s + rowA));   // 16B-aligned: A%4==0, rows 1KB
        const float4 qb = __ldg((const float4*)(s + rowB));

        float ca = 0.0f, cb = 0.0f;
        if (need_clean) {
            ca = __ldg(s + cleanA);
            cb = __ldg(s + cleanB);
        }

        // extract v(xa), v(xb) from each row's window (m is per-thread constant)
        const float va0 = (m == 0) ? qa.x : (m == 1) ? qa.y : (m == 2) ? qa.z : qa.w;
        const float vb0 = (m == 0) ? qb.x : (m == 1) ? qb.y : (m == 2) ? qb.z : qb.w;
        const float va1 = !adv ? va0 : ((m == 0) ? qa.y : (m == 1) ? qa.z : (m == 2) ? qa.w : ca);
        const float vb1 = !adv ? vb0 : ((m == 0) ? qb.y : (m == 1) ? qb.z : (m == 2) ? qb.w : cb);

        o[c * PLANE] = w00 * va0 + w01 * va1 + w10 * vb0 + w11 * vb1;
        s += PLANE;
    }
}

extern "C" void kernel_launch(void* const* d_in, const int* in_sizes, int n_in,
                              void* d_out, int out_size)
{
    const float* src  = (const float*)d_in[0];
    const float* flow = (const float*)d_in[1];
    float* out = (float*)d_out;

    dim3 grid(H_, C_ / CPT, B_);   // (256, 8, 8)
    dim3 block(W_);                // 256 threads, one per x
    st_w4_kernel<<<grid, block>>>(src, flow, out);
}

// round 11
// speedup vs baseline: 1.8158x; 1.5787x over previous
#include <cuda_runtime.h>

// SpatialTransformer: out[b,c,y,x] = bilinear_sample_zeros(src[b,c], y+flow[b,0,y,x], x+flow[b,1,y,x])
// src [8,64,256,256] f32, flow [8,2,256,256] f32, out [8,64,256,256] f32.
//
// R10: R2 structure (thread = one (b,y,x) for 8 channels, warp = 32 consecutive x),
// with the two same-row x-taps fetched by ONE LDG.64 at the 8B-aligned window
// (xa & ~1) — which provably has the same 32B-sector footprint as a scalar tap —
// plus a predicated half-warp LDG.32 cleanup for odd-xa lanes.

#define B_ 8
#define C_ 64
#define H_ 256
#define W_ 256
#define PLANE (H_ * W_)
#define CPT 8   // channels per thread

__global__ __launch_bounds__(256) void st_p2_kernel(
    const float* __restrict__ src,
    const float* __restrict__ flow,
    float* __restrict__ out)
{
    const int x  = threadIdx.x;        // 0..255
    const int y  = blockIdx.x;         // 0..255
    const int cg = blockIdx.y;         // 0..7   (channel group)
    const int b  = blockIdx.z;         // 0..7

    // ---- per-(b,y,x) prologue (identical to R2) ----
    const int fbase = b * 2 * PLANE + y * W_ + x;
    const float py = (float)y + __ldg(flow + fbase);           // flow ch 0 = dy
    const float px = (float)x + __ldg(flow + fbase + PLANE);   // flow ch 1 = dx

    const float y0f = floorf(py);
    const float x0f = floorf(px);
    float wy1 = py - y0f;
    float wx1 = px - x0f;
    float wy0 = 1.0f - wy1;
    float wx0 = 1.0f - wx1;

    const int y0 = (int)y0f;
    const int x0 = (int)x0f;
    const int y1 = y0 + 1;
    const int x1 = x0 + 1;

    // zeros padding folded into 1D weights
    wy0 = ((unsigned)y0 < (unsigned)H_) ? wy0 : 0.0f;
    wy1 = ((unsigned)y1 < (unsigned)H_) ? wy1 : 0.0f;
    wx0 = ((unsigned)x0 < (unsigned)W_) ? wx0 : 0.0f;
    wx1 = ((unsigned)x1 < (unsigned)W_) ? wx1 : 0.0f;

    const float w00 = wy0 * wx0;
    const float w01 = wy0 * wx1;
    const float w10 = wy1 * wx0;
    const float w11 = wy1 * wx1;

    // clamped coords (invalid taps carry weight 0)
    const int ya = min(max(y0, 0), H_ - 1);
    const int yb = min(max(y1, 0), H_ - 1);
    const int xa = min(max(x0, 0), W_ - 1);
    const int xb = min(max(x1, 0), W_ - 1);

    const bool odd   = (xa & 1);
    const bool adv   = (xb != xa);        // second x-tap is xa+1
    const bool need2 = adv && odd;        // xa+1 falls outside the float2 window

    const int rowA2  = ya * W_ + (xa & ~1);   // 8B-aligned window, row y0
    const int rowB2  = yb * W_ + (xa & ~1);   // 8B-aligned window, row y1
    const int cleanA = ya * W_ + xb;          // scalar tap for odd lanes
    const int cleanB = yb * W_ + xb;

    // ---- channel loop ----
    const int c0 = cg * CPT;
    const float* s = src + (size_t)(b * C_ + c0) * PLANE;
    float*       o = out + (size_t)(b * C_ + c0) * PLANE + y * W_ + x;

    #pragma unroll
    for (int c = 0; c < CPT; ++c) {
        const float2 pa = __ldg((const float2*)(s + rowA2));   // covers (xa&~1, xa&~1 +1)
        const float2 pb = __ldg((const float2*)(s + rowB2));

        float ca = 0.0f, cb = 0.0f;
        if (need2) {               // ~50% of lanes; predicated LDG.32
            ca = __ldg(s + cleanA);
            cb = __ldg(s + cleanB);
        }

        const float va0 = odd ? pa.y : pa.x;                   // v(ya, xa)
        const float vb0 = odd ? pb.y : pb.x;                   // v(yb, xa)
        const float va1 = !adv ? va0 : (odd ? ca : pa.y);      // v(ya, xb)
        const float vb1 = !adv ? vb0 : (odd ? cb : pb.y);      // v(yb, xb)

        o[c * PLANE] = w00 * va0 + w01 * va1 + w10 * vb0 + w11 * vb1;
        s += PLANE;
    }
}

extern "C" void kernel_launch(void* const* d_in, const int* in_sizes, int n_in,
                              void* d_out, int out_size)
{
    const float* src  = (const float*)d_in[0];
    const float* flow = (const float*)d_in[1];
    float* out = (float*)d_out;

    dim3 grid(H_, C_ / CPT, B_);   // (256, 8, 8)
    dim3 block(W_);                // 256 threads, one per x
    st_p2_kernel<<<grid, block>>>(src, flow, out);
}